// round 13
// baseline (speedup 1.0000x reference)
#include <cuda_runtime.h>
#include <cuda_bf16.h>
#include <math.h>

#define BB 2
#define TT 2048
#define DIM 1024
#define NH 16
#define HKV 4
#define HD 64
#define NQKV 1536   // 1024 q + 256 k + 256 v

// ---------------- scratch (device globals, no allocation) ----------------
__device__ __nv_bfloat16 g_wbf[NQKV * DIM];   // quantized qkv weights as exact bf16 ints
__device__ float g_wsc[NQKV];                 // per-row scales
__device__ __nv_bfloat16 g_wpbf[DIM * DIM];   // quantized proj weights
__device__ float g_wpsc[DIM];
__device__ float g_qkv[BB * TT * NQKV];       // fused q|k|v activations per token
__device__ float g_yo[BB * TT * DIM];

// exact 10000^(-j/16) = 10^(-j/4)
__device__ __constant__ float c_invfreq[16] = {
    1.0f, 0.5623413252f, 0.3162277660f, 0.1778279410f,
    0.1f, 0.05623413252f, 0.03162277660f, 0.01778279410f,
    0.01f, 5.623413252e-3f, 3.162277660e-3f, 1.778279410e-3f,
    1e-3f, 5.623413252e-4f, 3.162277660e-4f, 1.778279410e-4f};

// ---------------- bf16 split helpers ----------------
__device__ __forceinline__ void splitbf(float x, float y, unsigned& hi, unsigned& lo) {
    __nv_bfloat162 h = __floats2bfloat162_rn(x, y);
    float hx = __low2float(h), hy = __high2float(h);
    __nv_bfloat162 l = __floats2bfloat162_rn(x - hx, y - hy);
    hi = *reinterpret_cast<unsigned*>(&h);
    lo = *reinterpret_cast<unsigned*>(&l);
}

#define MMA_BF16(C, A0, A1, A2, A3, B0, B1)                                   \
    asm volatile(                                                             \
        "mma.sync.aligned.m16n8k16.row.col.f32.bf16.bf16.f32 "                \
        "{%0,%1,%2,%3}, {%4,%5,%6,%7}, {%8,%9}, {%0,%1,%2,%3};\n"             \
        : "+f"(C[0]), "+f"(C[1]), "+f"(C[2]), "+f"(C[3])                      \
        : "r"(A0), "r"(A1), "r"(A2), "r"(A3), "r"(B0), "r"(B1))

__device__ __forceinline__ void ldsm4(unsigned& r0, unsigned& r1, unsigned& r2, unsigned& r3,
                                      const unsigned* p) {
    unsigned addr = (unsigned)__cvta_generic_to_shared(p);
    asm volatile("ldmatrix.sync.aligned.m8n8.x4.shared.b16 {%0,%1,%2,%3}, [%4];"
                 : "=r"(r0), "=r"(r1), "=r"(r2), "=r"(r3) : "r"(addr));
}

// ---------------- fake_quant: all weight rows in one launch ----------------
__global__ __launch_bounds__(256) void quant_all_kernel(const float* __restrict__ wq,
                                                        const float* __restrict__ wk,
                                                        const float* __restrict__ wv,
                                                        const float* __restrict__ wp) {
    __shared__ float red[256];
    int r = blockIdx.x;
    const float* src;
    float halfv;
    __nv_bfloat16* dst;
    float* scd;
    int dr;
    if (r < 1024)      { src = wq + (size_t)r * DIM;          halfv = 32.f; dst = g_wbf;  scd = g_wsc;  dr = r; }
    else if (r < 1280) { src = wk + (size_t)(r - 1024) * DIM; halfv = 32.f; dst = g_wbf;  scd = g_wsc;  dr = r; }
    else if (r < 1536) { src = wv + (size_t)(r - 1280) * DIM; halfv = 16.f; dst = g_wbf;  scd = g_wsc;  dr = r; }
    else               { src = wp + (size_t)(r - 1536) * DIM; halfv = 16.f; dst = g_wpbf; scd = g_wpsc; dr = r - 1536; }

    float m = 0.f;
    for (int c = threadIdx.x; c < DIM; c += 256) m = fmaxf(m, fabsf(src[c]));
    red[threadIdx.x] = m;
    __syncthreads();
    for (int s = 128; s > 0; s >>= 1) {
        if (threadIdx.x < s) red[threadIdx.x] = fmaxf(red[threadIdx.x], red[threadIdx.x + s]);
        __syncthreads();
    }
    float wmax = fmaxf(red[0], 1e-5f);
    float sc = halfv / wmax, isc = wmax / halfv;
    for (int c = threadIdx.x; c < DIM; c += 256) {
        float q = rintf(src[c] * sc);
        q = fminf(fmaxf(q, -halfv), halfv - 1.f);
        dst[(size_t)dr * DIM + c] = __float2bfloat16(q);   // exact integer
    }
    if (threadIdx.x == 0) scd[dr] = isc;
}

// ---------------- 2x-bf16 GEMM: C[M,N] = (A @ Qbf^T) * diag(scale) ---------
#define KP 20

__global__ void __launch_bounds__(256) bf16_gemm_wq(const float* __restrict__ A,
                                                    const __nv_bfloat16* __restrict__ B,
                                                    const float* __restrict__ bsc,
                                                    float* __restrict__ C,
                                                    int M, int N, int K) {
    extern __shared__ unsigned smu[];
    unsigned* Ah = smu;                   // [2][128][KP]
    unsigned* Al = smu + 2 * 128 * KP;
    unsigned* Bh = smu + 4 * 128 * KP;    // [2][128][KP]

    const int tid = threadIdx.x;
    const int lane = tid & 31;
    const int wid = tid >> 5;
    const int wm = wid & 1;
    const int wn = wid >> 1;
    const int qr = lane >> 2;
    const int qc = lane & 3;
    const int m0 = blockIdx.y * 128, n0 = blockIdx.x * 128;
    const int lrow = tid >> 3;
    const int lkf = (tid & 7) * 4;
    const int kp0 = (tid & 7) * 2;
    const int brow = tid >> 1;
    const int bq = (tid & 1) * 2;

    const int lt = lane >> 3, lr = lane & 7;
    const int baseA = (wm * 64 + lr + (lt & 1) * 8) * KP + (lt >> 1) * 4;
    const int baseB = (wn * 32 + lr) * KP + (lt & 1) * 4;
    const int jrowB = (lt >> 1) * 8 * KP;

    float acc[4][4][4] = {};
    float4 ra[4];
    uint4 rbv[2];
    const int ntile = K / 32;

#pragma unroll
    for (int p = 0; p < 4; p++)
        ra[p] = *reinterpret_cast<const float4*>(A + (size_t)(m0 + lrow + p * 32) * K + lkf);
    {
        const uint4* bp = reinterpret_cast<const uint4*>(B + (size_t)(n0 + brow) * K);
        rbv[0] = bp[bq]; rbv[1] = bp[bq + 1];
    }
#pragma unroll
    for (int p = 0; p < 4; p++) {
        int row = lrow + p * 32;
        unsigned h0, l0, h1, l1;
        splitbf(ra[p].x, ra[p].y, h0, l0);
        splitbf(ra[p].z, ra[p].w, h1, l1);
        Ah[row * KP + kp0] = h0; Ah[row * KP + kp0 + 1] = h1;
        Al[row * KP + kp0] = l0; Al[row * KP + kp0 + 1] = l1;
    }
    *reinterpret_cast<uint4*>(Bh + brow * KP + bq * 4) = rbv[0];
    *reinterpret_cast<uint4*>(Bh + brow * KP + bq * 4 + 4) = rbv[1];
    __syncthreads();

    for (int t = 0; t < ntile; t++) {
        if (t + 1 < ntile) {
            int koff = (t + 1) * 32;
#pragma unroll
            for (int p = 0; p < 4; p++)
                ra[p] = *reinterpret_cast<const float4*>(A + (size_t)(m0 + lrow + p * 32) * K + koff + lkf);
            const uint4* bp = reinterpret_cast<const uint4*>(B + (size_t)(n0 + brow) * K + koff);
            rbv[0] = bp[bq]; rbv[1] = bp[bq + 1];
        }
        const unsigned* ah_b = Ah + (t & 1) * 128 * KP;
        const unsigned* al_b = Al + (t & 1) * 128 * KP;
        const unsigned* bh_b = Bh + (t & 1) * 128 * KP;
#pragma unroll
        for (int ks = 0; ks < 2; ks++) {
            unsigned afh[4][4], afl[4][4], bfh[4][2];
#pragma unroll
            for (int i = 0; i < 4; i++) {
                int o = baseA + i * 16 * KP + ks * 8;
                ldsm4(afh[i][0], afh[i][1], afh[i][2], afh[i][3], ah_b + o);
                ldsm4(afl[i][0], afl[i][1], afl[i][2], afl[i][3], al_b + o);
            }
#pragma unroll
            for (int jp = 0; jp < 2; jp++) {
                int o = baseB + (jp * 2) * 8 * KP + jrowB + ks * 8;
                ldsm4(bfh[2 * jp][0], bfh[2 * jp][1], bfh[2 * jp + 1][0], bfh[2 * jp + 1][1], bh_b + o);
            }
#pragma unroll
            for (int i = 0; i < 4; i++)
#pragma unroll
                for (int j = 0; j < 4; j++) {
                    MMA_BF16(acc[i][j], afh[i][0], afh[i][1], afh[i][2], afh[i][3], bfh[j][0], bfh[j][1]);
                    MMA_BF16(acc[i][j], afl[i][0], afl[i][1], afl[i][2], afl[i][3], bfh[j][0], bfh[j][1]);
                }
        }
        if (t + 1 < ntile) {
            unsigned* ah_n = Ah + ((t + 1) & 1) * 128 * KP;
            unsigned* al_n = Al + ((t + 1) & 1) * 128 * KP;
            unsigned* bh_n = Bh + ((t + 1) & 1) * 128 * KP;
#pragma unroll
            for (int p = 0; p < 4; p++) {
                int row = lrow + p * 32;
                unsigned h0, l0, h1, l1;
                splitbf(ra[p].x, ra[p].y, h0, l0);
                splitbf(ra[p].z, ra[p].w, h1, l1);
                ah_n[row * KP + kp0] = h0; ah_n[row * KP + kp0 + 1] = h1;
                al_n[row * KP + kp0] = l0; al_n[row * KP + kp0 + 1] = l1;
            }
            *reinterpret_cast<uint4*>(bh_n + brow * KP + bq * 4) = rbv[0];
            *reinterpret_cast<uint4*>(bh_n + brow * KP + bq * 4 + 4) = rbv[1];
        }
        __syncthreads();
    }

#pragma unroll
    for (int i = 0; i < 4; i++) {
        int row = m0 + wm * 64 + i * 16 + qr;
#pragma unroll
        for (int j = 0; j < 4; j++) {
            int col = n0 + wn * 32 + j * 8 + 2 * qc;
            float2 s = *reinterpret_cast<const float2*>(bsc + col);
            *reinterpret_cast<float2*>(C + (size_t)row * N + col) =
                make_float2(acc[i][j][0] * s.x, acc[i][j][1] * s.y);
            *reinterpret_cast<float2*>(C + (size_t)(row + 8) * N + col) =
                make_float2(acc[i][j][2] * s.x, acc[i][j][3] * s.y);
        }
    }
}

// ---------------- per-head RMSNorm + RoPE + gain (q and k) ----------------
__global__ __launch_bounds__(128) void norm_rope_kernel(const float* __restrict__ gain) {
    int gw = (blockIdx.x * 128 + threadIdx.x) >> 5;
    int lane = threadIdx.x & 31;
    const int NQ = BB * TT * NH;
    const int NK = BB * TT * HKV;
    float* ptr;
    float g;
    int t;
    if (gw < NQ) {
        int h = gw % NH;
        int bt = gw / NH;
        t = bt % TT;
        ptr = g_qkv + (size_t)bt * NQKV + h * HD;
        g = gain[h];
    } else {
        int w2 = gw - NQ;
        if (w2 >= NK) return;
        int hk = w2 % HKV;
        int bt = w2 / HKV;
        t = bt % TT;
        ptr = g_qkv + (size_t)bt * NQKV + 1024 + hk * HD;
        g = 1.f;
    }
    float2 v = reinterpret_cast<const float2*>(ptr)[lane];
    float ss = v.x * v.x + v.y * v.y;
#pragma unroll
    for (int o = 16; o; o >>= 1) ss += __shfl_xor_sync(0xffffffffu, ss, o);
    float r = rsqrtf(ss * (1.f / 64.f) + 1.19209290e-07f);
    float n0 = v.x * r, n1 = v.y * r;
    float p0 = __shfl_xor_sync(0xffffffffu, n0, 8);
    float p1 = __shfl_xor_sync(0xffffffffu, n1, 8);
    float o0 = n0, o1 = n1;
    if (lane < 16) {
        int i0 = (2 * lane) & 15;
        float a0 = (float)t * c_invfreq[i0];
        float a1 = (float)t * c_invfreq[(i0 + 1) & 15];
        float c0, s0, c1, s1;
        sincosf(a0, &s0, &c0);
        sincosf(a1, &s1, &c1);
        if (lane < 8) {
            o0 = n0 * c0 + p0 * s0;
            o1 = n1 * c1 + p1 * s1;
        } else {
            o0 = -p0 * s0 + n0 * c0;
            o1 = -p1 * s1 + n1 * c1;
        }
    }
    reinterpret_cast<float2*>(ptr)[lane] = make_float2(o0 * g, o1 * g);
}

// ---------------- tensor-core causal flash attention (3x-bf16) -------------
// BM=128 (8 warps x m16), BN=64, D=64. Register-resident P.
// K smem: [key][dim-pairs] stride 36; V smem: TRANSPOSED [dim][key-pairs]
// stride 36 -> both QK and PV fragments load via ldmatrix.x4 (no scalar LDS).
#define KSTR 36
#define VST 36
#define BUFU (2 * 64 * KSTR + 2 * 64 * VST)   // 9216 uint32 per buffer

__global__ void __launch_bounds__(256) attn_tc_kernel() {
    extern __shared__ unsigned smu[];

    const int b = blockIdx.z, h = blockIdx.y;
    const int qt = (gridDim.x - 1) - blockIdx.x;   // heavy blocks first
    const int hk = h >> 2;
    const int tid = threadIdx.x;
    const int lane = tid & 31;
    const int w = tid >> 5;
    const int qr = lane >> 2;
    const int qc = lane & 3;
    const int qbase = qt * 128 + w * 16;
    const int qi0 = qbase + qr, qi1 = qbase + qr + 8;

    const int lt = lane >> 3, lr = lane & 7;
    const int baseK = lr * KSTR + (lt & 1) * 4 + (lt >> 1) * 8 * KSTR;
    const int baseV = (lr + (lt >> 1) * 8) * VST + (lt & 1) * 4;

    // staging index precompute
    int rrK[4], dfK[4];
#pragma unroll
    for (int i = 0; i < 4; i++) { int it = tid + i * 256; rrK[i] = it >> 4; dfK[i] = (it & 15) * 4; }
    const int dimV = tid & 63;          // V staging: dim handled by this thread
    const int kgb = tid >> 6;           // key-group base (4 keys per group)

    // Q fragments (bf16 hi/lo packed pairs)
    unsigned qh[4][4], ql[4][4];
    {
        const float* Qp = g_qkv + ((size_t)b * TT + qbase) * NQKV + h * HD;
#pragma unroll
        for (int ks = 0; ks < 4; ks++) {
            int c0 = ks * 16 + 2 * qc;
            float2 x0 = *reinterpret_cast<const float2*>(Qp + (size_t)qr * NQKV + c0);
            float2 x1 = *reinterpret_cast<const float2*>(Qp + (size_t)(qr + 8) * NQKV + c0);
            float2 x2 = *reinterpret_cast<const float2*>(Qp + (size_t)qr * NQKV + c0 + 8);
            float2 x3 = *reinterpret_cast<const float2*>(Qp + (size_t)(qr + 8) * NQKV + c0 + 8);
            splitbf(x0.x, x0.y, qh[ks][0], ql[ks][0]);
            splitbf(x1.x, x1.y, qh[ks][1], ql[ks][1]);
            splitbf(x2.x, x2.y, qh[ks][2], ql[ks][2]);
            splitbf(x3.x, x3.y, qh[ks][3], ql[ks][3]);
        }
    }

    float yac[8][4] = {};
    float m0 = -1e30f, m1 = -1e30f, l0 = 0.f, l1 = 0.f;

    const int ktmax = 2 * qt + 1;
    float4 rk[4];
    float rv[4][4];

    // ---- prologue: load + stage tile 0 ----
#pragma unroll
    for (int i = 0; i < 4; i++)
        rk[i] = *reinterpret_cast<const float4*>(
            g_qkv + ((size_t)b * TT + rrK[i]) * NQKV + 1024 + hk * HD + dfK[i]);
#pragma unroll
    for (int it = 0; it < 4; it++) {
        int kg = kgb + it * 4;
#pragma unroll
        for (int j = 0; j < 4; j++)
            rv[it][j] = g_qkv[((size_t)b * TT + 4 * kg + j) * NQKV + 1280 + hk * HD + dimV];
    }
    {
        unsigned* Kh = smu;
        unsigned* Kl = smu + 64 * KSTR;
        unsigned* Vth = smu + 2 * 64 * KSTR;
        unsigned* Vtl = smu + 2 * 64 * KSTR + 64 * VST;
#pragma unroll
        for (int i = 0; i < 4; i++) {
            unsigned h0, l0r, h1, l1r;
            splitbf(rk[i].x, rk[i].y, h0, l0r);
            splitbf(rk[i].z, rk[i].w, h1, l1r);
            int o = rrK[i] * KSTR + dfK[i] / 2;
            Kh[o] = h0; Kh[o + 1] = h1; Kl[o] = l0r; Kl[o + 1] = l1r;
        }
#pragma unroll
        for (int it = 0; it < 4; it++) {
            int kg = kgb + it * 4;
            unsigned h0, l0r, h1, l1r;
            splitbf(rv[it][0], rv[it][1], h0, l0r);
            splitbf(rv[it][2], rv[it][3], h1, l1r);
            *reinterpret_cast<uint2*>(Vth + dimV * VST + 2 * kg) = make_uint2(h0, h1);
            *reinterpret_cast<uint2*>(Vtl + dimV * VST + 2 * kg) = make_uint2(l0r, l1r);
        }
    }
    __syncthreads();

    for (int kt = 0; kt <= ktmax; kt++) {
        // ---- prefetch tile kt+1 into registers ----
        if (kt < ktmax) {
#pragma unroll
            for (int i = 0; i < 4; i++)
                rk[i] = *reinterpret_cast<const float4*>(
                    g_qkv + ((size_t)b * TT + (kt + 1) * 64 + rrK[i]) * NQKV + 1024 + hk * HD + dfK[i]);
#pragma unroll
            for (int it = 0; it < 4; it++) {
                int kg = kgb + it * 4;
#pragma unroll
                for (int j = 0; j < 4; j++)
                    rv[it][j] = g_qkv[((size_t)b * TT + (kt + 1) * 64 + 4 * kg + j) * NQKV + 1280 + hk * HD + dimV];
            }
        }

        const unsigned* Khi = smu + (kt & 1) * BUFU;
        const unsigned* Klo = Khi + 64 * KSTR;
        const unsigned* Vth = Khi + 2 * 64 * KSTR;
        const unsigned* Vtl = Khi + 2 * 64 * KSTR + 64 * VST;

        if (kt * 64 <= qbase + 15) {
            // ---- S = Q K^T (3x bf16, K frags via ldmatrix) ----
            float sf[8][4] = {};
#pragma unroll
            for (int ks = 0; ks < 4; ks++) {
#pragma unroll
                for (int jp = 0; jp < 4; jp++) {
                    int o = baseK + (jp * 2) * 8 * KSTR + ks * 8;
                    unsigned kh[4], kl[4];
                    ldsm4(kh[0], kh[1], kh[2], kh[3], Khi + o);
                    ldsm4(kl[0], kl[1], kl[2], kl[3], Klo + o);
                    MMA_BF16(sf[2 * jp], qh[ks][0], qh[ks][1], qh[ks][2], qh[ks][3], kh[0], kh[1]);
                    MMA_BF16(sf[2 * jp], ql[ks][0], ql[ks][1], ql[ks][2], ql[ks][3], kh[0], kh[1]);
                    MMA_BF16(sf[2 * jp], qh[ks][0], qh[ks][1], qh[ks][2], qh[ks][3], kl[0], kl[1]);
                    MMA_BF16(sf[2 * jp + 1], qh[ks][0], qh[ks][1], qh[ks][2], qh[ks][3], kh[2], kh[3]);
                    MMA_BF16(sf[2 * jp + 1], ql[ks][0], ql[ks][1], ql[ks][2], ql[ks][3], kh[2], kh[3]);
                    MMA_BF16(sf[2 * jp + 1], qh[ks][0], qh[ks][1], qh[ks][2], qh[ks][3], kl[2], kl[3]);
                }
            }
            // ---- scale + causal mask ----
#pragma unroll
            for (int j = 0; j < 8; j++) {
                int kj = kt * 64 + j * 8 + 2 * qc;
                sf[j][0] = (kj     <= qi0) ? sf[j][0] * 0.125f : -1e30f;
                sf[j][1] = (kj + 1 <= qi0) ? sf[j][1] * 0.125f : -1e30f;
                sf[j][2] = (kj     <= qi1) ? sf[j][2] * 0.125f : -1e30f;
                sf[j][3] = (kj + 1 <= qi1) ? sf[j][3] * 0.125f : -1e30f;
            }
            // ---- online softmax ----
            float cm0 = -1e30f, cm1 = -1e30f;
#pragma unroll
            for (int j = 0; j < 8; j++) {
                cm0 = fmaxf(cm0, fmaxf(sf[j][0], sf[j][1]));
                cm1 = fmaxf(cm1, fmaxf(sf[j][2], sf[j][3]));
            }
            cm0 = fmaxf(cm0, __shfl_xor_sync(0xffffffffu, cm0, 1));
            cm0 = fmaxf(cm0, __shfl_xor_sync(0xffffffffu, cm0, 2));
            cm1 = fmaxf(cm1, __shfl_xor_sync(0xffffffffu, cm1, 1));
            cm1 = fmaxf(cm1, __shfl_xor_sync(0xffffffffu, cm1, 2));
            float mn0 = fmaxf(m0, cm0), mn1 = fmaxf(m1, cm1);
            float a0 = __expf(m0 - mn0), a1 = __expf(m1 - mn1);
#pragma unroll
            for (int jd = 0; jd < 8; jd++) {
                yac[jd][0] *= a0; yac[jd][1] *= a0;
                yac[jd][2] *= a1; yac[jd][3] *= a1;
            }
            unsigned ph0[8], ph1[8], pl0[8], pl1[8];
            float rs0 = 0.f, rs1 = 0.f;
#pragma unroll
            for (int j = 0; j < 8; j++) {
                float p0 = __expf(sf[j][0] - mn0);
                float p1 = __expf(sf[j][1] - mn0);
                float p2 = __expf(sf[j][2] - mn1);
                float p3 = __expf(sf[j][3] - mn1);
                rs0 += p0 + p1; rs1 += p2 + p3;
                splitbf(p0, p1, ph0[j], pl0[j]);
                splitbf(p2, p3, ph1[j], pl1[j]);
            }
            rs0 += __shfl_xor_sync(0xffffffffu, rs0, 1);
            rs0 += __shfl_xor_sync(0xffffffffu, rs0, 2);
            rs1 += __shfl_xor_sync(0xffffffffu, rs1, 1);
            rs1 += __shfl_xor_sync(0xffffffffu, rs1, 2);
            l0 = l0 * a0 + rs0;
            l1 = l1 * a1 + rs1;
            m0 = mn0; m1 = mn1;
            // ---- Y += P V (3x bf16): P from regs, V frags via ldmatrix ----
#pragma unroll
            for (int ks = 0; ks < 4; ks++) {
                unsigned a0h = ph0[2 * ks], a1h = ph1[2 * ks];
                unsigned a2h = ph0[2 * ks + 1], a3h = ph1[2 * ks + 1];
                unsigned a0l = pl0[2 * ks], a1l = pl1[2 * ks];
                unsigned a2l = pl0[2 * ks + 1], a3l = pl1[2 * ks + 1];
#pragma unroll
                for (int jdp = 0; jdp < 4; jdp++) {
                    int o = baseV + jdp * 16 * VST + ks * 8;
                    unsigned vh[4], vl[4];
                    ldsm4(vh[0], vh[1], vh[2], vh[3], Vth + o);
                    ldsm4(vl[0], vl[1], vl[2], vl[3], Vtl + o);
                    MMA_BF16(yac[2 * jdp],     a0h, a1h, a2h, a3h, vh[0], vh[1]);
                    MMA_BF16(yac[2 * jdp],     a0l, a1l, a2l, a3l, vh[0], vh[1]);
                    MMA_BF16(yac[2 * jdp],     a0h, a1h, a2h, a3h, vl[0], vl[1]);
                    MMA_BF16(yac[2 * jdp + 1], a0h, a1h, a2h, a3h, vh[2], vh[3]);
                    MMA_BF16(yac[2 * jdp + 1], a0l, a1l, a2l, a3l, vh[2], vh[3]);
                    MMA_BF16(yac[2 * jdp + 1], a0h, a1h, a2h, a3h, vl[2], vl[3]);
                }
            }
        }

        // ---- stage tile kt+1 into the other buffer ----
        if (kt < ktmax) {
            unsigned* Kh = smu + ((kt + 1) & 1) * BUFU;
            unsigned* Kl = Kh + 64 * KSTR;
            unsigned* Vh = Kh + 2 * 64 * KSTR;
            unsigned* Vl = Kh + 2 * 64 * KSTR + 64 * VST;
#pragma unroll
            for (int i = 0; i < 4; i++) {
                unsigned h0, l0r, h1, l1r;
                splitbf(rk[i].x, rk[i].y, h0, l0r);
                splitbf(rk[i].z, rk[i].w, h1, l1r);
                int o = rrK[i] * KSTR + dfK[i] / 2;
                Kh[o] = h0; Kh[o + 1] = h1; Kl[o] = l0r; Kl[o + 1] = l1r;
            }
#pragma unroll
            for (int it = 0; it < 4; it++) {
                int kg = kgb + it * 4;
                unsigned h0, l0r, h1, l1r;
                splitbf(rv[it][0], rv[it][1], h0, l0r);
                splitbf(rv[it][2], rv[it][3], h1, l1r);
                *reinterpret_cast<uint2*>(Vh + dimV * VST + 2 * kg) = make_uint2(h0, h1);
                *reinterpret_cast<uint2*>(Vl + dimV * VST + 2 * kg) = make_uint2(l0r, l1r);
            }
        }
        __syncthreads();
    }

    // ---- epilogue: normalize + fused v-direction rejection ----
    float inv0 = 1.f / l0, inv1 = 1.f / l1;
    float2 y0[8], y1[8], v0[8], v1[8];
    {
        const float* Vq0 = g_qkv + ((size_t)b * TT + qi0) * NQKV + 1280 + hk * HD;
        const float* Vq1 = g_qkv + ((size_t)b * TT + qi1) * NQKV + 1280 + hk * HD;
#pragma unroll
        for (int jd = 0; jd < 8; jd++) {
            int col = jd * 8 + 2 * qc;
            y0[jd] = make_float2(yac[jd][0] * inv0, yac[jd][1] * inv0);
            y1[jd] = make_float2(yac[jd][2] * inv1, yac[jd][3] * inv1);
            v0[jd] = *reinterpret_cast<const float2*>(Vq0 + col);
            v1[jd] = *reinterpret_cast<const float2*>(Vq1 + col);
        }
    }
    float ns0 = 0.f, ns1 = 0.f, dt0 = 0.f, dt1 = 0.f;
#pragma unroll
    for (int jd = 0; jd < 8; jd++) {
        ns0 += v0[jd].x * v0[jd].x + v0[jd].y * v0[jd].y;
        ns1 += v1[jd].x * v1[jd].x + v1[jd].y * v1[jd].y;
        dt0 += y0[jd].x * v0[jd].x + y0[jd].y * v0[jd].y;
        dt1 += y1[jd].x * v1[jd].x + y1[jd].y * v1[jd].y;
    }
    ns0 += __shfl_xor_sync(0xffffffffu, ns0, 1); ns0 += __shfl_xor_sync(0xffffffffu, ns0, 2);
    ns1 += __shfl_xor_sync(0xffffffffu, ns1, 1); ns1 += __shfl_xor_sync(0xffffffffu, ns1, 2);
    dt0 += __shfl_xor_sync(0xffffffffu, dt0, 1); dt0 += __shfl_xor_sync(0xffffffffu, dt0, 2);
    dt1 += __shfl_xor_sync(0xffffffffu, dt1, 1); dt1 += __shfl_xor_sync(0xffffffffu, dt1, 2);
    float in0 = 1.f / fmaxf(sqrtf(ns0), 1e-12f);
    float in1 = 1.f / fmaxf(sqrtf(ns1), 1e-12f);
    float c0 = dt0 * in0 * in0, c1 = dt1 * in1 * in1;

    float* Yp0 = g_yo + ((size_t)b * TT + qi0) * DIM + h * HD;
    float* Yp1 = g_yo + ((size_t)b * TT + qi1) * DIM + h * HD;
#pragma unroll
    for (int jd = 0; jd < 8; jd++) {
        int col = jd * 8 + 2 * qc;
        *reinterpret_cast<float2*>(Yp0 + col) =
            make_float2(y0[jd].x - c0 * v0[jd].x, y0[jd].y - c0 * v0[jd].y);
        *reinterpret_cast<float2*>(Yp1 + col) =
            make_float2(y1[jd].x - c1 * v1[jd].x, y1[jd].y - c1 * v1[jd].y);
    }
}

// ---------------- launch ----------------
extern "C" void kernel_launch(void* const* d_in, const int* in_sizes, int n_in,
                              void* d_out, int out_size) {
    const float* x      = (const float*)d_in[0];
    const float* w_q    = (const float*)d_in[1];
    const float* w_k    = (const float*)d_in[2];
    const float* w_v    = (const float*)d_in[3];
    const float* w_proj = (const float*)d_in[4];
    const float* q_gain = (const float*)d_in[5];

    __nv_bfloat16 *wbf, *wpbf;
    float *wsc, *wpsc, *qkv, *yo;
    cudaGetSymbolAddress((void**)&wbf, g_wbf);
    cudaGetSymbolAddress((void**)&wsc, g_wsc);
    cudaGetSymbolAddress((void**)&wpbf, g_wpbf);
    cudaGetSymbolAddress((void**)&wpsc, g_wpsc);
    cudaGetSymbolAddress((void**)&qkv, g_qkv);
    cudaGetSymbolAddress((void**)&yo, g_yo);

    const int M = BB * TT;          // 4096
    const int SMEM = 6 * 128 * KP * sizeof(unsigned);     // 61440
    const int ASMEM = 2 * BUFU * sizeof(unsigned);        // 73728

    static bool attr_set = false;
    if (!attr_set) {
        cudaFuncSetAttribute(bf16_gemm_wq, cudaFuncAttributeMaxDynamicSharedMemorySize, SMEM);
        cudaFuncSetAttribute(attn_tc_kernel, cudaFuncAttributeMaxDynamicSharedMemorySize, ASMEM);
        attr_set = true;
    }

    quant_all_kernel<<<NQKV + DIM, 256>>>(w_q, w_k, w_v, w_proj);

    bf16_gemm_wq<<<dim3(NQKV / 128, M / 128), 256, SMEM>>>(x, wbf, wsc, qkv, M, NQKV, DIM);

    {
        int warps = BB * TT * (NH + HKV);
        norm_rope_kernel<<<warps / 4, 128>>>(q_gain);
    }

    attn_tc_kernel<<<dim3(TT / 128, NH, BB), 256, ASMEM>>>();

    bf16_gemm_wq<<<dim3(DIM / 128, M / 128), 256, SMEM>>>(yo, wpbf, wpsc, (float*)d_out, M, DIM, DIM);
}

// round 17
// speedup vs baseline: 1.0216x; 1.0216x over previous
#include <cuda_runtime.h>
#include <cuda_bf16.h>
#include <math.h>

#define BB 2
#define TT 2048
#define DIM 1024
#define NH 16
#define HKV 4
#define HD 64
#define NQKV 1536   // 1024 q + 256 k + 256 v

// ---------------- scratch (device globals, no allocation) ----------------
__device__ __nv_bfloat16 g_wbf[NQKV * DIM];   // quantized qkv weights as exact bf16 ints
__device__ float g_wsc[NQKV];                 // per-row scales
__device__ __nv_bfloat16 g_wpbf[DIM * DIM];   // quantized proj weights
__device__ float g_wpsc[DIM];
__device__ float g_qkv[BB * TT * NQKV];       // fused q|k|v activations per token
__device__ float g_yo[BB * TT * DIM];

// exact 10000^(-j/16) = 10^(-j/4)
__device__ __constant__ float c_invfreq[16] = {
    1.0f, 0.5623413252f, 0.3162277660f, 0.1778279410f,
    0.1f, 0.05623413252f, 0.03162277660f, 0.01778279410f,
    0.01f, 5.623413252e-3f, 3.162277660e-3f, 1.778279410e-3f,
    1e-3f, 5.623413252e-4f, 3.162277660e-4f, 1.778279410e-4f};

// ---------------- bf16 split helpers ----------------
__device__ __forceinline__ void splitbf(float x, float y, unsigned& hi, unsigned& lo) {
    __nv_bfloat162 h = __floats2bfloat162_rn(x, y);
    float hx = __low2float(h), hy = __high2float(h);
    __nv_bfloat162 l = __floats2bfloat162_rn(x - hx, y - hy);
    hi = *reinterpret_cast<unsigned*>(&h);
    lo = *reinterpret_cast<unsigned*>(&l);
}

#define MMA_BF16(C, A0, A1, A2, A3, B0, B1)                                   \
    asm volatile(                                                             \
        "mma.sync.aligned.m16n8k16.row.col.f32.bf16.bf16.f32 "                \
        "{%0,%1,%2,%3}, {%4,%5,%6,%7}, {%8,%9}, {%0,%1,%2,%3};\n"             \
        : "+f"(C[0]), "+f"(C[1]), "+f"(C[2]), "+f"(C[3])                      \
        : "r"(A0), "r"(A1), "r"(A2), "r"(A3), "r"(B0), "r"(B1))

__device__ __forceinline__ void ldsm4(unsigned& r0, unsigned& r1, unsigned& r2, unsigned& r3,
                                      const unsigned* p) {
    unsigned addr = (unsigned)__cvta_generic_to_shared(p);
    asm volatile("ldmatrix.sync.aligned.m8n8.x4.shared.b16 {%0,%1,%2,%3}, [%4];"
                 : "=r"(r0), "=r"(r1), "=r"(r2), "=r"(r3) : "r"(addr));
}

// ---------------- fake_quant: all weight rows in one launch ----------------
__global__ __launch_bounds__(256) void quant_all_kernel(const float* __restrict__ wq,
                                                        const float* __restrict__ wk,
                                                        const float* __restrict__ wv,
                                                        const float* __restrict__ wp) {
    __shared__ float red[256];
    int r = blockIdx.x;
    const float* src;
    float halfv;
    __nv_bfloat16* dst;
    float* scd;
    int dr;
    if (r < 1024)      { src = wq + (size_t)r * DIM;          halfv = 32.f; dst = g_wbf;  scd = g_wsc;  dr = r; }
    else if (r < 1280) { src = wk + (size_t)(r - 1024) * DIM; halfv = 32.f; dst = g_wbf;  scd = g_wsc;  dr = r; }
    else if (r < 1536) { src = wv + (size_t)(r - 1280) * DIM; halfv = 16.f; dst = g_wbf;  scd = g_wsc;  dr = r; }
    else               { src = wp + (size_t)(r - 1536) * DIM; halfv = 16.f; dst = g_wpbf; scd = g_wpsc; dr = r - 1536; }

    float m = 0.f;
    for (int c = threadIdx.x; c < DIM; c += 256) m = fmaxf(m, fabsf(src[c]));
    red[threadIdx.x] = m;
    __syncthreads();
    for (int s = 128; s > 0; s >>= 1) {
        if (threadIdx.x < s) red[threadIdx.x] = fmaxf(red[threadIdx.x], red[threadIdx.x + s]);
        __syncthreads();
    }
    float wmax = fmaxf(red[0], 1e-5f);
    float sc = halfv / wmax, isc = wmax / halfv;
    for (int c = threadIdx.x; c < DIM; c += 256) {
        float q = rintf(src[c] * sc);
        q = fminf(fmaxf(q, -halfv), halfv - 1.f);
        dst[(size_t)dr * DIM + c] = __float2bfloat16(q);   // exact integer
    }
    if (threadIdx.x == 0) scd[dr] = isc;
}

// ---------------- 2x-bf16 GEMM: C[M,N] = (A @ Qbf^T) * diag(scale) ---------
#define KP 20

__global__ void __launch_bounds__(256) bf16_gemm_wq(const float* __restrict__ A,
                                                    const __nv_bfloat16* __restrict__ B,
                                                    const float* __restrict__ bsc,
                                                    float* __restrict__ C,
                                                    int M, int N, int K) {
    extern __shared__ unsigned smu[];
    unsigned* Ah = smu;                   // [2][128][KP]
    unsigned* Al = smu + 2 * 128 * KP;
    unsigned* Bh = smu + 4 * 128 * KP;    // [2][128][KP]

    const int tid = threadIdx.x;
    const int lane = tid & 31;
    const int wid = tid >> 5;
    const int wm = wid & 1;
    const int wn = wid >> 1;
    const int qr = lane >> 2;
    const int qc = lane & 3;
    const int m0 = blockIdx.y * 128, n0 = blockIdx.x * 128;
    const int lrow = tid >> 3;
    const int lkf = (tid & 7) * 4;
    const int kp0 = (tid & 7) * 2;
    const int brow = tid >> 1;
    const int bq = (tid & 1) * 2;

    const int lt = lane >> 3, lr = lane & 7;
    const int baseA = (wm * 64 + lr + (lt & 1) * 8) * KP + (lt >> 1) * 4;
    const int baseB = (wn * 32 + lr) * KP + (lt & 1) * 4;
    const int jrowB = (lt >> 1) * 8 * KP;

    float acc[4][4][4] = {};
    float4 ra[4];
    uint4 rbv[2];
    const int ntile = K / 32;

#pragma unroll
    for (int p = 0; p < 4; p++)
        ra[p] = *reinterpret_cast<const float4*>(A + (size_t)(m0 + lrow + p * 32) * K + lkf);
    {
        const uint4* bp = reinterpret_cast<const uint4*>(B + (size_t)(n0 + brow) * K);
        rbv[0] = bp[bq]; rbv[1] = bp[bq + 1];
    }
#pragma unroll
    for (int p = 0; p < 4; p++) {
        int row = lrow + p * 32;
        unsigned h0, l0, h1, l1;
        splitbf(ra[p].x, ra[p].y, h0, l0);
        splitbf(ra[p].z, ra[p].w, h1, l1);
        Ah[row * KP + kp0] = h0; Ah[row * KP + kp0 + 1] = h1;
        Al[row * KP + kp0] = l0; Al[row * KP + kp0 + 1] = l1;
    }
    *reinterpret_cast<uint4*>(Bh + brow * KP + bq * 4) = rbv[0];
    *reinterpret_cast<uint4*>(Bh + brow * KP + bq * 4 + 4) = rbv[1];
    __syncthreads();

    for (int t = 0; t < ntile; t++) {
        if (t + 1 < ntile) {
            int koff = (t + 1) * 32;
#pragma unroll
            for (int p = 0; p < 4; p++)
                ra[p] = *reinterpret_cast<const float4*>(A + (size_t)(m0 + lrow + p * 32) * K + koff + lkf);
            const uint4* bp = reinterpret_cast<const uint4*>(B + (size_t)(n0 + brow) * K + koff);
            rbv[0] = bp[bq]; rbv[1] = bp[bq + 1];
        }
        const unsigned* ah_b = Ah + (t & 1) * 128 * KP;
        const unsigned* al_b = Al + (t & 1) * 128 * KP;
        const unsigned* bh_b = Bh + (t & 1) * 128 * KP;
#pragma unroll
        for (int ks = 0; ks < 2; ks++) {
            unsigned afh[4][4], afl[4][4], bfh[4][2];
#pragma unroll
            for (int i = 0; i < 4; i++) {
                int o = baseA + i * 16 * KP + ks * 8;
                ldsm4(afh[i][0], afh[i][1], afh[i][2], afh[i][3], ah_b + o);
                ldsm4(afl[i][0], afl[i][1], afl[i][2], afl[i][3], al_b + o);
            }
#pragma unroll
            for (int jp = 0; jp < 2; jp++) {
                int o = baseB + (jp * 2) * 8 * KP + jrowB + ks * 8;
                ldsm4(bfh[2 * jp][0], bfh[2 * jp][1], bfh[2 * jp + 1][0], bfh[2 * jp + 1][1], bh_b + o);
            }
#pragma unroll
            for (int i = 0; i < 4; i++)
#pragma unroll
                for (int j = 0; j < 4; j++) {
                    MMA_BF16(acc[i][j], afh[i][0], afh[i][1], afh[i][2], afh[i][3], bfh[j][0], bfh[j][1]);
                    MMA_BF16(acc[i][j], afl[i][0], afl[i][1], afl[i][2], afl[i][3], bfh[j][0], bfh[j][1]);
                }
        }
        if (t + 1 < ntile) {
            unsigned* ah_n = Ah + ((t + 1) & 1) * 128 * KP;
            unsigned* al_n = Al + ((t + 1) & 1) * 128 * KP;
            unsigned* bh_n = Bh + ((t + 1) & 1) * 128 * KP;
#pragma unroll
            for (int p = 0; p < 4; p++) {
                int row = lrow + p * 32;
                unsigned h0, l0, h1, l1;
                splitbf(ra[p].x, ra[p].y, h0, l0);
                splitbf(ra[p].z, ra[p].w, h1, l1);
                ah_n[row * KP + kp0] = h0; ah_n[row * KP + kp0 + 1] = h1;
                al_n[row * KP + kp0] = l0; al_n[row * KP + kp0 + 1] = l1;
            }
            *reinterpret_cast<uint4*>(bh_n + brow * KP + bq * 4) = rbv[0];
            *reinterpret_cast<uint4*>(bh_n + brow * KP + bq * 4 + 4) = rbv[1];
        }
        __syncthreads();
    }

#pragma unroll
    for (int i = 0; i < 4; i++) {
        int row = m0 + wm * 64 + i * 16 + qr;
#pragma unroll
        for (int j = 0; j < 4; j++) {
            int col = n0 + wn * 32 + j * 8 + 2 * qc;
            float2 s = *reinterpret_cast<const float2*>(bsc + col);
            *reinterpret_cast<float2*>(C + (size_t)row * N + col) =
                make_float2(acc[i][j][0] * s.x, acc[i][j][1] * s.y);
            *reinterpret_cast<float2*>(C + (size_t)(row + 8) * N + col) =
                make_float2(acc[i][j][2] * s.x, acc[i][j][3] * s.y);
        }
    }
}

// ---------------- per-head RMSNorm + RoPE + gain (q and k) ----------------
__global__ __launch_bounds__(128) void norm_rope_kernel(const float* __restrict__ gain) {
    int gw = (blockIdx.x * 128 + threadIdx.x) >> 5;
    int lane = threadIdx.x & 31;
    const int NQ = BB * TT * NH;
    const int NK = BB * TT * HKV;
    float* ptr;
    float g;
    int t;
    if (gw < NQ) {
        int h = gw % NH;
        int bt = gw / NH;
        t = bt % TT;
        ptr = g_qkv + (size_t)bt * NQKV + h * HD;
        g = gain[h];
    } else {
        int w2 = gw - NQ;
        if (w2 >= NK) return;
        int hk = w2 % HKV;
        int bt = w2 / HKV;
        t = bt % TT;
        ptr = g_qkv + (size_t)bt * NQKV + 1024 + hk * HD;
        g = 1.f;
    }
    float2 v = reinterpret_cast<const float2*>(ptr)[lane];
    float ss = v.x * v.x + v.y * v.y;
#pragma unroll
    for (int o = 16; o; o >>= 1) ss += __shfl_xor_sync(0xffffffffu, ss, o);
    float r = rsqrtf(ss * (1.f / 64.f) + 1.19209290e-07f);
    float n0 = v.x * r, n1 = v.y * r;
    float p0 = __shfl_xor_sync(0xffffffffu, n0, 8);
    float p1 = __shfl_xor_sync(0xffffffffu, n1, 8);
    float o0 = n0, o1 = n1;
    if (lane < 16) {
        int i0 = (2 * lane) & 15;
        float a0 = (float)t * c_invfreq[i0];
        float a1 = (float)t * c_invfreq[(i0 + 1) & 15];
        float c0, s0, c1, s1;
        sincosf(a0, &s0, &c0);
        sincosf(a1, &s1, &c1);
        if (lane < 8) {
            o0 = n0 * c0 + p0 * s0;
            o1 = n1 * c1 + p1 * s1;
        } else {
            o0 = -p0 * s0 + n0 * c0;
            o1 = -p1 * s1 + n1 * c1;
        }
    }
    reinterpret_cast<float2*>(ptr)[lane] = make_float2(o0 * g, o1 * g);
}

// ---------------- tensor-core causal flash attention (3x-bf16) -------------
// BM=64 (4 warps x m16), BN=64, D=64, 128 threads, single-buffer smem,
// __launch_bounds__(128,3) -> 3 independent blocks per SM (latency overlap).
// K smem: [key][dim-pairs] stride 36; V smem: transposed [dim][key-pairs].
#define KSTR 36
#define VST 36

__global__ void __launch_bounds__(128, 3) attn_tc_kernel() {
    extern __shared__ unsigned smu[];
    unsigned* Khi = smu;                        // [64][KSTR]
    unsigned* Klo = smu + 64 * KSTR;
    unsigned* Vth = smu + 2 * 64 * KSTR;        // [64][VST] transposed
    unsigned* Vtl = smu + 2 * 64 * KSTR + 64 * VST;

    const int b = blockIdx.z, h = blockIdx.y;
    const int qt = (gridDim.x - 1) - blockIdx.x;   // heavy blocks first
    const int hk = h >> 2;
    const int tid = threadIdx.x;
    const int lane = tid & 31;
    const int w = tid >> 5;                     // 0..3
    const int qr = lane >> 2;
    const int qc = lane & 3;
    const int qbase = qt * 64 + w * 16;
    const int qi0 = qbase + qr, qi1 = qbase + qr + 8;

    const int lt = lane >> 3, lr = lane & 7;
    const int baseK = lr * KSTR + (lt & 1) * 4 + (lt >> 1) * 8 * KSTR;
    const int baseV = (lr + (lt >> 1) * 8) * VST + (lt & 1) * 4;

    const int dimV = tid & 63;                  // V staging dim
    const int kgb = tid >> 6;                   // 0..1

    // Q fragments (bf16 hi/lo packed pairs)
    unsigned qh[4][4], ql[4][4];
    {
        const float* Qp = g_qkv + ((size_t)b * TT + qbase) * NQKV + h * HD;
#pragma unroll
        for (int ks = 0; ks < 4; ks++) {
            int c0 = ks * 16 + 2 * qc;
            float2 x0 = *reinterpret_cast<const float2*>(Qp + (size_t)qr * NQKV + c0);
            float2 x1 = *reinterpret_cast<const float2*>(Qp + (size_t)(qr + 8) * NQKV + c0);
            float2 x2 = *reinterpret_cast<const float2*>(Qp + (size_t)qr * NQKV + c0 + 8);
            float2 x3 = *reinterpret_cast<const float2*>(Qp + (size_t)(qr + 8) * NQKV + c0 + 8);
            splitbf(x0.x, x0.y, qh[ks][0], ql[ks][0]);
            splitbf(x1.x, x1.y, qh[ks][1], ql[ks][1]);
            splitbf(x2.x, x2.y, qh[ks][2], ql[ks][2]);
            splitbf(x3.x, x3.y, qh[ks][3], ql[ks][3]);
        }
    }

    float yac[8][4] = {};
    float m0 = -1e30f, m1 = -1e30f, l0 = 0.f, l1 = 0.f;

    const int ktmax = qt;
    for (int kt = 0; kt <= ktmax; kt++) {
        // ---- stage K tile (128 threads, 8 slots each) ----
#pragma unroll
        for (int i = 0; i < 8; i++) {
            int it = tid + i * 128;
            int rr = it >> 4;
            int df = (it & 15) * 4;
            float4 kv = *reinterpret_cast<const float4*>(
                g_qkv + ((size_t)b * TT + kt * 64 + rr) * NQKV + 1024 + hk * HD + df);
            unsigned h0, l0r, h1, l1r;
            splitbf(kv.x, kv.y, h0, l0r);
            splitbf(kv.z, kv.w, h1, l1r);
            int o = rr * KSTR + df / 2;
            Khi[o] = h0; Khi[o + 1] = h1;
            Klo[o] = l0r; Klo[o + 1] = l1r;
        }
        // ---- stage V tile transposed ----
#pragma unroll
        for (int it = 0; it < 8; it++) {
            int kg = kgb + it * 2;              // key pair-group 0..15 (4 keys each)
            size_t base = ((size_t)b * TT + kt * 64 + 4 * kg) * NQKV + 1280 + hk * HD + dimV;
            float v0 = g_qkv[base];
            float v1 = g_qkv[base + NQKV];
            float v2 = g_qkv[base + 2 * NQKV];
            float v3 = g_qkv[base + 3 * NQKV];
            unsigned h0, l0r, h1, l1r;
            splitbf(v0, v1, h0, l0r);
            splitbf(v2, v3, h1, l1r);
            *reinterpret_cast<uint2*>(Vth + dimV * VST + 2 * kg) = make_uint2(h0, h1);
            *reinterpret_cast<uint2*>(Vtl + dimV * VST + 2 * kg) = make_uint2(l0r, l1r);
        }
        __syncthreads();

        {
            // ---- S = Q K^T (3x bf16, K frags via ldmatrix) ----
            float sf[8][4] = {};
#pragma unroll
            for (int ks = 0; ks < 4; ks++) {
#pragma unroll
                for (int jp = 0; jp < 4; jp++) {
                    int o = baseK + (jp * 2) * 8 * KSTR + ks * 8;
                    unsigned kh[4], kl[4];
                    ldsm4(kh[0], kh[1], kh[2], kh[3], Khi + o);
                    ldsm4(kl[0], kl[1], kl[2], kl[3], Klo + o);
                    MMA_BF16(sf[2 * jp], qh[ks][0], qh[ks][1], qh[ks][2], qh[ks][3], kh[0], kh[1]);
                    MMA_BF16(sf[2 * jp], ql[ks][0], ql[ks][1], ql[ks][2], ql[ks][3], kh[0], kh[1]);
                    MMA_BF16(sf[2 * jp], qh[ks][0], qh[ks][1], qh[ks][2], qh[ks][3], kl[0], kl[1]);
                    MMA_BF16(sf[2 * jp + 1], qh[ks][0], qh[ks][1], qh[ks][2], qh[ks][3], kh[2], kh[3]);
                    MMA_BF16(sf[2 * jp + 1], ql[ks][0], ql[ks][1], ql[ks][2], ql[ks][3], kh[2], kh[3]);
                    MMA_BF16(sf[2 * jp + 1], qh[ks][0], qh[ks][1], qh[ks][2], qh[ks][3], kl[2], kl[3]);
                }
            }
            // ---- scale + causal mask ----
#pragma unroll
            for (int j = 0; j < 8; j++) {
                int kj = kt * 64 + j * 8 + 2 * qc;
                sf[j][0] = (kj     <= qi0) ? sf[j][0] * 0.125f : -1e30f;
                sf[j][1] = (kj + 1 <= qi0) ? sf[j][1] * 0.125f : -1e30f;
                sf[j][2] = (kj     <= qi1) ? sf[j][2] * 0.125f : -1e30f;
                sf[j][3] = (kj + 1 <= qi1) ? sf[j][3] * 0.125f : -1e30f;
            }
            // ---- online softmax ----
            float cm0 = -1e30f, cm1 = -1e30f;
#pragma unroll
            for (int j = 0; j < 8; j++) {
                cm0 = fmaxf(cm0, fmaxf(sf[j][0], sf[j][1]));
                cm1 = fmaxf(cm1, fmaxf(sf[j][2], sf[j][3]));
            }
            cm0 = fmaxf(cm0, __shfl_xor_sync(0xffffffffu, cm0, 1));
            cm0 = fmaxf(cm0, __shfl_xor_sync(0xffffffffu, cm0, 2));
            cm1 = fmaxf(cm1, __shfl_xor_sync(0xffffffffu, cm1, 1));
            cm1 = fmaxf(cm1, __shfl_xor_sync(0xffffffffu, cm1, 2));
            float mn0 = fmaxf(m0, cm0), mn1 = fmaxf(m1, cm1);
            float a0 = __expf(m0 - mn0), a1 = __expf(m1 - mn1);
#pragma unroll
            for (int jd = 0; jd < 8; jd++) {
                yac[jd][0] *= a0; yac[jd][1] *= a0;
                yac[jd][2] *= a1; yac[jd][3] *= a1;
            }
            unsigned ph0[8], ph1[8], pl0[8], pl1[8];
            float rs0 = 0.f, rs1 = 0.f;
#pragma unroll
            for (int j = 0; j < 8; j++) {
                float p0 = __expf(sf[j][0] - mn0);
                float p1 = __expf(sf[j][1] - mn0);
                float p2 = __expf(sf[j][2] - mn1);
                float p3 = __expf(sf[j][3] - mn1);
                rs0 += p0 + p1; rs1 += p2 + p3;
                splitbf(p0, p1, ph0[j], pl0[j]);
                splitbf(p2, p3, ph1[j], pl1[j]);
            }
            rs0 += __shfl_xor_sync(0xffffffffu, rs0, 1);
            rs0 += __shfl_xor_sync(0xffffffffu, rs0, 2);
            rs1 += __shfl_xor_sync(0xffffffffu, rs1, 1);
            rs1 += __shfl_xor_sync(0xffffffffu, rs1, 2);
            l0 = l0 * a0 + rs0;
            l1 = l1 * a1 + rs1;
            m0 = mn0; m1 = mn1;
            // ---- Y += P V (3x bf16): P from regs, V frags via ldmatrix ----
#pragma unroll
            for (int ks = 0; ks < 4; ks++) {
                unsigned a0h = ph0[2 * ks], a1h = ph1[2 * ks];
                unsigned a2h = ph0[2 * ks + 1], a3h = ph1[2 * ks + 1];
                unsigned a0l = pl0[2 * ks], a1l = pl1[2 * ks];
                unsigned a2l = pl0[2 * ks + 1], a3l = pl1[2 * ks + 1];
#pragma unroll
                for (int jdp = 0; jdp < 4; jdp++) {
                    int o = baseV + jdp * 16 * VST + ks * 8;
                    unsigned vh[4], vl[4];
                    ldsm4(vh[0], vh[1], vh[2], vh[3], Vth + o);
                    ldsm4(vl[0], vl[1], vl[2], vl[3], Vtl + o);
                    MMA_BF16(yac[2 * jdp],     a0h, a1h, a2h, a3h, vh[0], vh[1]);
                    MMA_BF16(yac[2 * jdp],     a0l, a1l, a2l, a3l, vh[0], vh[1]);
                    MMA_BF16(yac[2 * jdp],     a0h, a1h, a2h, a3h, vl[0], vl[1]);
                    MMA_BF16(yac[2 * jdp + 1], a0h, a1h, a2h, a3h, vh[2], vh[3]);
                    MMA_BF16(yac[2 * jdp + 1], a0l, a1l, a2l, a3l, vh[2], vh[3]);
                    MMA_BF16(yac[2 * jdp + 1], a0h, a1h, a2h, a3h, vl[2], vl[3]);
                }
            }
        }
        __syncthreads();
    }

    // ---- epilogue: normalize + fused v-direction rejection ----
    float inv0 = 1.f / l0, inv1 = 1.f / l1;
    float2 y0[8], y1[8], v0[8], v1[8];
    {
        const float* Vq0 = g_qkv + ((size_t)b * TT + qi0) * NQKV + 1280 + hk * HD;
        const float* Vq1 = g_qkv + ((size_t)b * TT + qi1) * NQKV + 1280 + hk * HD;
#pragma unroll
        for (int jd = 0; jd < 8; jd++) {
            int col = jd * 8 + 2 * qc;
            y0[jd] = make_float2(yac[jd][0] * inv0, yac[jd][1] * inv0);
            y1[jd] = make_float2(yac[jd][2] * inv1, yac[jd][3] * inv1);
            v0[jd] = *reinterpret_cast<const float2*>(Vq0 + col);
            v1[jd] = *reinterpret_cast<const float2*>(Vq1 + col);
        }
    }
    float ns0 = 0.f, ns1 = 0.f, dt0 = 0.f, dt1 = 0.f;
#pragma unroll
    for (int jd = 0; jd < 8; jd++) {
        ns0 += v0[jd].x * v0[jd].x + v0[jd].y * v0[jd].y;
        ns1 += v1[jd].x * v1[jd].x + v1[jd].y * v1[jd].y;
        dt0 += y0[jd].x * v0[jd].x + y0[jd].y * v0[jd].y;
        dt1 += y1[jd].x * v1[jd].x + y1[jd].y * v1[jd].y;
    }
    ns0 += __shfl_xor_sync(0xffffffffu, ns0, 1); ns0 += __shfl_xor_sync(0xffffffffu, ns0, 2);
    ns1 += __shfl_xor_sync(0xffffffffu, ns1, 1); ns1 += __shfl_xor_sync(0xffffffffu, ns1, 2);
    dt0 += __shfl_xor_sync(0xffffffffu, dt0, 1); dt0 += __shfl_xor_sync(0xffffffffu, dt0, 2);
    dt1 += __shfl_xor_sync(0xffffffffu, dt1, 1); dt1 += __shfl_xor_sync(0xffffffffu, dt1, 2);
    float in0 = 1.f / fmaxf(sqrtf(ns0), 1e-12f);
    float in1 = 1.f / fmaxf(sqrtf(ns1), 1e-12f);
    float c0 = dt0 * in0 * in0, c1 = dt1 * in1 * in1;

    float* Yp0 = g_yo + ((size_t)b * TT + qi0) * DIM + h * HD;
    float* Yp1 = g_yo + ((size_t)b * TT + qi1) * DIM + h * HD;
#pragma unroll
    for (int jd = 0; jd < 8; jd++) {
        int col = jd * 8 + 2 * qc;
        *reinterpret_cast<float2*>(Yp0 + col) =
            make_float2(y0[jd].x - c0 * v0[jd].x, y0[jd].y - c0 * v0[jd].y);
        *reinterpret_cast<float2*>(Yp1 + col) =
            make_float2(y1[jd].x - c1 * v1[jd].x, y1[jd].y - c1 * v1[jd].y);
    }
}

// ---------------- launch ----------------
extern "C" void kernel_launch(void* const* d_in, const int* in_sizes, int n_in,
                              void* d_out, int out_size) {
    const float* x      = (const float*)d_in[0];
    const float* w_q    = (const float*)d_in[1];
    const float* w_k    = (const float*)d_in[2];
    const float* w_v    = (const float*)d_in[3];
    const float* w_proj = (const float*)d_in[4];
    const float* q_gain = (const float*)d_in[5];

    __nv_bfloat16 *wbf, *wpbf;
    float *wsc, *wpsc, *qkv, *yo;
    cudaGetSymbolAddress((void**)&wbf, g_wbf);
    cudaGetSymbolAddress((void**)&wsc, g_wsc);
    cudaGetSymbolAddress((void**)&wpbf, g_wpbf);
    cudaGetSymbolAddress((void**)&wpsc, g_wpsc);
    cudaGetSymbolAddress((void**)&qkv, g_qkv);
    cudaGetSymbolAddress((void**)&yo, g_yo);

    const int M = BB * TT;          // 4096
    const int SMEM = 6 * 128 * KP * sizeof(unsigned);            // 61440
    const int ASMEM = (2 * 64 * KSTR + 2 * 64 * VST) * sizeof(unsigned); // 36864

    static bool attr_set = false;
    if (!attr_set) {
        cudaFuncSetAttribute(bf16_gemm_wq, cudaFuncAttributeMaxDynamicSharedMemorySize, SMEM);
        cudaFuncSetAttribute(attn_tc_kernel, cudaFuncAttributeMaxDynamicSharedMemorySize, ASMEM);
        attr_set = true;
    }

    quant_all_kernel<<<NQKV + DIM, 256>>>(w_q, w_k, w_v, w_proj);

    bf16_gemm_wq<<<dim3(NQKV / 128, M / 128), 256, SMEM>>>(x, wbf, wsc, qkv, M, NQKV, DIM);

    {
        int warps = BB * TT * (NH + HKV);
        norm_rope_kernel<<<warps / 4, 128>>>(q_gain);
    }

    // BM=64, 128 threads, 3 blocks/SM
    attn_tc_kernel<<<dim3(TT / 64, NH, BB), 128, ASMEM>>>();

    bf16_gemm_wq<<<dim3(DIM / 128, M / 128), 256, SMEM>>>(yo, wpbf, wpsc, (float*)d_out, M, DIM, DIM);
}